// round 9
// baseline (speedup 1.0000x reference)
#include <cuda_runtime.h>

#define NN   116
#define NE   6670
#define HID  64
#define ENCD 122

// ---- device scratch ----
__device__ float g_gE[NE * 5];
__device__ float g_dv[NN];
__device__ __align__(16) float g_x1[NN * HID];
__device__ __align__(16) float g_Wz[124 * HID];  // [W_enc; b_enc; 0] @ W1
__device__ __align__(16) float g_Wc[HID * 4];    // W2 @ Wl
__device__ float g_S[NN * 5];

__device__ __forceinline__ int rowoff(int a) { return a * (231 - a) / 2; }
__device__ __forceinline__ int eix(int a, int b) { return rowoff(a) + (b - a - 1); }

// ============================================================================
// K0: weight-only precompute (overlaps k1 via PDL).
//  blocks 0..30: Wz[c,h] (124x64 = 31*256 threads exactly)
//  block 31:     Wc = W2@Wl (256 thr) + bias seed out = bl + b2@Wl (thr 0..3)
// ============================================================================
__global__ void __launch_bounds__(256, 1) k0(
    const float* __restrict__ W_enc, const float* __restrict__ b_enc,
    const float* __restrict__ W1, const float* __restrict__ W2,
    const float* __restrict__ b2, const float* __restrict__ Wl,
    const float* __restrict__ bl, float* __restrict__ out)
{
    const int b = blockIdx.x, t = threadIdx.x;
    if (b < 31) {
        int id = b * 256 + t;
        int c = id >> 6, h = id & 63;
        float s = 0.f;
        if (c < 122) {
            #pragma unroll
            for (int m = 0; m < HID; m++) s += W_enc[c * HID + m] * W1[m * HID + h];
        } else if (c == 122) {
            #pragma unroll
            for (int m = 0; m < HID; m++) s += b_enc[m] * W1[m * HID + h];
        }
        g_Wz[id] = s;
    } else {
        int k = t >> 2, o = t & 3;
        float s = 0.f;
        #pragma unroll
        for (int m = 0; m < HID; m++) s += W2[k * HID + m] * Wl[m * 4 + o];
        g_Wc[t] = s;
        if (t < 4) {
            float v = bl[t];
            #pragma unroll
            for (int m = 0; m < HID; m++) v += b2[m] * Wl[m * 4 + t];
            out[t] = v;
        }
    }
}

// ============================================================================
// K1 (PDL after k0, 512 thr): block per node i.
//   edge stage (d1 row + gE row) -> M stage -> [wait k0] -> x1 = relu(b1+M@Wz) -> dv
// ============================================================================
__global__ void __launch_bounds__(512, 1) k1(
    const float* __restrict__ enc, const float* __restrict__ ea,
    const float* __restrict__ b1, const float* __restrict__ p1,
    const float* __restrict__ We, const float* __restrict__ pe)
{
    __shared__ float sd1[116];
    __shared__ float sMp[4 * 123];
    __shared__ float sM[124];          // [122]=s_i (bias lane), [123]=0
    __shared__ float sp[512];
    __shared__ float sx1[64];

    const int i = blockIdx.x, t = threadIdx.x;

    // d1 row + gE row (1 edge per thread; gE written once by row-owner block)
    if (t < 115) {
        int k = t + (t >= i);
        int a = min(i, k), b = max(i, k);
        int e = eix(a, b);
        const float* A = ea + e * 5;
        float a5[5], r5[5];
        #pragma unroll
        for (int c = 0; c < 5; c++) { a5[c] = A[c]; r5[c] = fmaxf(a5[c], 0.f); }
        sd1[t] = a5[0] * __ldg(&p1[0]) + a5[1] * __ldg(&p1[1]) + a5[2] * __ldg(&p1[2])
               + a5[3] * __ldg(&p1[3]) + a5[4] * __ldg(&p1[4]);
        if (a == i) {
            #pragma unroll
            for (int c2 = 0; c2 < 5; c2++) {
                float g = r5[0] * __ldg(&We[c2]) + r5[1] * __ldg(&We[5 + c2])
                        + r5[2] * __ldg(&We[10 + c2]) + r5[3] * __ldg(&We[15 + c2])
                        + r5[4] * __ldg(&We[20 + c2]);
                g_gE[e * 5 + c2] = g;
            }
        }
    }
    __syncthreads();

    // M stage: 4 threads per col, 29 unrolled iters each (123 cols; col 122 = sum d1)
    if (t < 492) {
        int c = t >> 2, q = t & 3;
        int u0 = q * 29;
        float s = 0.f;
        if (c < 122) {
            #pragma unroll
            for (int j = 0; j < 29; ++j) {
                int u = u0 + j;
                if (u < 115) {
                    int k = u + (u >= i);
                    s += sd1[u] * enc[k * ENCD + c];
                }
            }
        } else {
            #pragma unroll
            for (int j = 0; j < 29; ++j) {
                int u = u0 + j;
                if (u < 115) s += sd1[u];
            }
        }
        sMp[q * 123 + c] = s;
    }
    __syncthreads();
    if (t < 123) sM[t] = sMp[t] + sMp[123 + t] + sMp[246 + t] + sMp[369 + t];
    if (t == 123) sM[123] = 0.f;

    cudaGridDependencySynchronize();   // Wz ready (k0 finished during edge/M stages)
    __syncthreads();

    // x1 = relu(b1 + M @ Wz) : 8 groups x 16 unrolled cols per m
    {
        int m = t & 63, g = t >> 6;
        float s = 0.f;
        #pragma unroll
        for (int j = 0; j < 16; ++j) {
            int c = g * 16 + j;
            if (c < 124) s += sM[c] * g_Wz[c * HID + m];
        }
        sp[g * 64 + m] = s;
    }
    __syncthreads();
    if (t < HID) {
        float s = sp[t];
        #pragma unroll
        for (int g = 1; g < 8; ++g) s += sp[g * 64 + t];
        float x = fmaxf(b1[t] + s, 0.f);
        sx1[t] = x;
        g_x1[i * HID + t] = x;
    }
    __syncthreads();

    // warp 0: dv = x1 . pe
    if (t < 32) {
        float s = sx1[t] * pe[t] + sx1[t + 32] * pe[t + 32];
        #pragma unroll
        for (int off = 16; off; off >>= 1) s += __shfl_xor_sync(0xffffffffu, s, off);
        if (t == 0) g_dv[i] = s;
    }
}

// ============================================================================
// K2 (PDL): S[i,c] = sum over 115 edges of gE/(max(dv_i,dv_k,0)+eps)
// ============================================================================
__global__ void __launch_bounds__(128, 1) k2(float* dummy)
{
    cudaGridDependencySynchronize();

    __shared__ float sdv[NN];
    __shared__ float wsum[4 * 5];
    const int i = blockIdx.x, t = threadIdx.x;
    const int wq = t >> 5, lane = t & 31;

    if (t < NN) sdv[t] = g_dv[t];
    __syncthreads();

    float a5[5] = {0.f, 0.f, 0.f, 0.f, 0.f};
    if (t < 115) {
        int k = t + (t >= i);
        int a = min(i, k), b = max(i, k);
        int e = eix(a, b);
        float inv = 1.f / (fmaxf(fmaxf(sdv[i], sdv[k]), 0.f) + 1e-10f);
        #pragma unroll
        for (int c = 0; c < 5; c++) a5[c] = g_gE[e * 5 + c] * inv;
    }
    #pragma unroll
    for (int c = 0; c < 5; c++) {
        #pragma unroll
        for (int off = 16; off; off >>= 1) a5[c] += __shfl_xor_sync(0xffffffffu, a5[c], off);
        if (lane == 0) wsum[wq * 5 + c] = a5[c];
    }
    __syncthreads();
    if (t < 5) g_S[i * 5 + t] = wsum[t] + wsum[5 + t] + wsum[10 + t] + wsum[15 + t];
}

// ============================================================================
// K3 (PDL): D[i]; q[i] = x1[i]@Wc inline; out[o] += D * q[o] / NN
// ============================================================================
__global__ void __launch_bounds__(128, 1) k3(
    const float* __restrict__ be, const float* __restrict__ p2,
    float* __restrict__ out)
{
    cudaGridDependencySynchronize();

    __shared__ float sdv[NN];
    __shared__ float sS[NN * 5];
    __shared__ float sx1r[HID];
    __shared__ float sWc[HID * 4];
    __shared__ float wred[4];
    const int i = blockIdx.x, t = threadIdx.x;
    const int wq = t >> 5, lane = t & 31;

    if (t < NN) sdv[t] = g_dv[t];
    for (int u = t; u < NN * 5; u += 128) sS[u] = g_S[u];
    if (t < HID) sx1r[t] = g_x1[i * HID + t];
    sWc[t] = g_Wc[t];
    sWc[t + 128] = g_Wc[t + 128];
    __syncthreads();

    float dvi = sdv[i];
    float partv = 0.f;
    if (t < 115) {
        int k = t + (t >= i);
        int a = min(i, k), b = max(i, k);
        int e = eix(a, b);
        float dvk = sdv[k];
        float inv = 1.f / (fmaxf(fmaxf(dvi, dvk), 0.f) + 1e-10f);
        #pragma unroll
        for (int c = 0; c < 5; c++) {
            float hh = g_gE[e * 5 + c] * inv;
            float v = dvi * (sS[i * 5 + c] - hh) + dvk * (sS[k * 5 + c] - hh) + __ldg(&be[c]);
            partv += fmaxf(v, 0.f) * __ldg(&p2[c]);
        }
    }
    #pragma unroll
    for (int off = 16; off; off >>= 1) partv += __shfl_xor_sync(0xffffffffu, partv, off);
    if (lane == 0) wred[wq] = partv;
    __syncthreads();

    {
        int o = wq;
        float qv = sx1r[lane] * sWc[lane * 4 + o] + sx1r[lane + 32] * sWc[(lane + 32) * 4 + o];
        #pragma unroll
        for (int off = 16; off; off >>= 1) qv += __shfl_xor_sync(0xffffffffu, qv, off);
        if (lane == 0) {
            float D = wred[0] + wred[1] + wred[2] + wred[3];
            atomicAdd(&out[o], D * qv * (1.0f / (float)NN));
        }
    }
}

extern "C" void kernel_launch(void* const* d_in, const int* in_sizes, int n_in,
                              void* d_out, int out_size) {
    const float* enc   = (const float*)d_in[0];
    const float* ea    = (const float*)d_in[1];
    // d_in[2] = edge_index (triu order, closed-form reproduced) — unused
    const float* W_enc = (const float*)d_in[3];
    const float* b_enc = (const float*)d_in[4];
    const float* W1    = (const float*)d_in[5];
    const float* b1    = (const float*)d_in[6];
    const float* p1    = (const float*)d_in[7];
    const float* We    = (const float*)d_in[8];
    const float* be    = (const float*)d_in[9];
    const float* pe    = (const float*)d_in[10];
    const float* W2    = (const float*)d_in[11];
    const float* b2    = (const float*)d_in[12];
    const float* p2    = (const float*)d_in[13];
    const float* Wl    = (const float*)d_in[14];
    const float* bl    = (const float*)d_in[15];
    float* out = (float*)d_out;

    cudaLaunchAttribute attr[1];
    attr[0].id = cudaLaunchAttributeProgrammaticStreamSerialization;
    attr[0].val.programmaticStreamSerializationAllowed = 1;

    k0<<<32, 256>>>(W_enc, b_enc, W1, W2, b2, Wl, bl, out);
    {
        cudaLaunchConfig_t cfg = {};
        cfg.gridDim = dim3(NN); cfg.blockDim = dim3(512);
        cfg.attrs = attr; cfg.numAttrs = 1; cfg.stream = 0;
        cudaLaunchKernelEx(&cfg, k1, enc, ea, b1, p1, We, pe);
    }
    {
        cudaLaunchConfig_t cfg = {};
        cfg.gridDim = dim3(NN); cfg.blockDim = dim3(128);
        cfg.attrs = attr; cfg.numAttrs = 1; cfg.stream = 0;
        cudaLaunchKernelEx(&cfg, k2, (float*)d_out);
    }
    {
        cudaLaunchConfig_t cfg = {};
        cfg.gridDim = dim3(NN); cfg.blockDim = dim3(128);
        cfg.attrs = attr; cfg.numAttrs = 1; cfg.stream = 0;
        cudaLaunchKernelEx(&cfg, k3, be, p2, out);
    }
}

// round 10
// speedup vs baseline: 1.0133x; 1.0133x over previous
#include <cuda_runtime.h>

#define NN   116
#define NE   6670
#define HID  64
#define ENCD 122
#define NWZB 8                 // Wz producer blocks inside k1

// ---- device scratch ----
__device__ float g_gE[NE * 5];
__device__ float g_dv[NN];
__device__ __align__(16) float g_x1[NN * HID];
__device__ __align__(16) float g_Wz[124 * HID];  // [W_enc; b_enc; 0] @ W1
__device__ __align__(16) float g_Wc[HID * 4];    // W2 @ Wl
__device__ float g_S[NN * 5];
__device__ unsigned g_done = 0;                  // Wz producer count; reset by k3

__device__ __forceinline__ int rowoff(int a) { return a * (231 - a) / 2; }
__device__ __forceinline__ int eix(int a, int b) { return rowoff(a) + (b - a - 1); }

// ============================================================================
// K1 (124 blocks x 512 thr):
//  blocks 116..123: produce Wz = [W_enc; b_enc; 0] @ W1 (992 dots each), bump g_done
//  blocks 0..115 (node i): edge stage -> M stage -> spin(g_done==8) ->
//                          x1 = relu(b1 + M @ Wz) -> dv
// ============================================================================
__global__ void __launch_bounds__(512, 1) k1(
    const float* __restrict__ enc, const float* __restrict__ ea,
    const float* __restrict__ W_enc, const float* __restrict__ b_enc,
    const float* __restrict__ W1, const float* __restrict__ b1,
    const float* __restrict__ p1, const float* __restrict__ We,
    const float* __restrict__ pe)
{
    const int i = blockIdx.x, t = threadIdx.x;

    if (i >= NN) {                       // ---- Wz producer block ----
        int bi = i - NN;                 // 0..7
        #pragma unroll
        for (int j = 0; j < 2; ++j) {
            int idx = bi * 992 + j * 512 + t;
            if (idx < (bi + 1) * 992 && idx < 124 * HID) {
                int c = idx >> 6, h = idx & 63;
                float s = 0.f;
                if (c < 122) {
                    #pragma unroll
                    for (int m = 0; m < HID; m++) s += W_enc[c * HID + m] * W1[m * HID + h];
                } else if (c == 122) {
                    #pragma unroll
                    for (int m = 0; m < HID; m++) s += b_enc[m] * W1[m * HID + h];
                }
                g_Wz[idx] = s;
            }
        }
        __syncthreads();
        __threadfence();
        if (t == 0) atomicAdd(&g_done, 1u);
        return;
    }

    __shared__ float sd1[116];
    __shared__ float sMp[4 * 123];
    __shared__ float sM[124];          // [122]=s_i (bias lane), [123]=0
    __shared__ float sp[512];
    __shared__ float sx1[64];

    // d1 row + gE row (1 edge per thread; gE written once by row-owner block)
    if (t < 115) {
        int k = t + (t >= i);
        int a = min(i, k), b = max(i, k);
        int e = eix(a, b);
        const float* A = ea + e * 5;
        float a5[5], r5[5];
        #pragma unroll
        for (int c = 0; c < 5; c++) { a5[c] = A[c]; r5[c] = fmaxf(a5[c], 0.f); }
        sd1[t] = a5[0] * __ldg(&p1[0]) + a5[1] * __ldg(&p1[1]) + a5[2] * __ldg(&p1[2])
               + a5[3] * __ldg(&p1[3]) + a5[4] * __ldg(&p1[4]);
        if (a == i) {
            #pragma unroll
            for (int c2 = 0; c2 < 5; c2++) {
                float g = r5[0] * __ldg(&We[c2]) + r5[1] * __ldg(&We[5 + c2])
                        + r5[2] * __ldg(&We[10 + c2]) + r5[3] * __ldg(&We[15 + c2])
                        + r5[4] * __ldg(&We[20 + c2]);
                g_gE[e * 5 + c2] = g;
            }
        }
    }
    __syncthreads();

    // M stage: 4 threads per col, 29 unrolled iters each (123 cols; col 122 = sum d1)
    if (t < 492) {
        int c = t >> 2, q = t & 3;
        int u0 = q * 29;
        float s = 0.f;
        if (c < 122) {
            #pragma unroll
            for (int j = 0; j < 29; ++j) {
                int u = u0 + j;
                if (u < 115) {
                    int k = u + (u >= i);
                    s += sd1[u] * enc[k * ENCD + c];
                }
            }
        } else {
            #pragma unroll
            for (int j = 0; j < 29; ++j) {
                int u = u0 + j;
                if (u < 115) s += sd1[u];
            }
        }
        sMp[q * 123 + c] = s;
    }
    __syncthreads();
    if (t < 123) sM[t] = sMp[t] + sMp[123 + t] + sMp[246 + t] + sMp[369 + t];
    if (t == 123) sM[123] = 0.f;

    // wait for Wz producers (expected already done: they ran during edge+M)
    if (t == 0) {
        while (*(volatile unsigned*)&g_done < NWZB) {}
        __threadfence();
    }
    __syncthreads();

    // x1 = relu(b1 + M @ Wz) : 8 groups x 16 unrolled cols per m
    {
        int m = t & 63, g = t >> 6;
        float s = 0.f;
        #pragma unroll
        for (int j = 0; j < 16; ++j) {
            int c = g * 16 + j;
            if (c < 124) s += sM[c] * g_Wz[c * HID + m];
        }
        sp[g * 64 + m] = s;
    }
    __syncthreads();
    if (t < HID) {
        float s = sp[t];
        #pragma unroll
        for (int g = 1; g < 8; ++g) s += sp[g * 64 + t];
        float x = fmaxf(b1[t] + s, 0.f);
        sx1[t] = x;
        g_x1[i * HID + t] = x;
    }
    __syncthreads();

    // warp 0: dv = x1 . pe
    if (t < 32) {
        float s = sx1[t] * pe[t] + sx1[t + 32] * pe[t + 32];
        #pragma unroll
        for (int off = 16; off; off >>= 1) s += __shfl_xor_sync(0xffffffffu, s, off);
        if (t == 0) g_dv[i] = s;
    }
}

// ============================================================================
// K2 (PDL): blocks 0..115: S[i,c]; blocks 116,117: Wc = W2@Wl + bias seed
// (independent of k1 -> no grid sync -> overlap with k1 tail)
// ============================================================================
__global__ void __launch_bounds__(128, 1) k2(
    const float* __restrict__ W2, const float* __restrict__ b2,
    const float* __restrict__ Wl, const float* __restrict__ bl,
    float* __restrict__ out)
{
    const int i = blockIdx.x, t = threadIdx.x;

    if (i >= NN) {
        int idx = (i - NN) * 128 + t;    // 0..255
        int k = idx >> 2, o = idx & 3;
        float s = 0.f;
        #pragma unroll
        for (int m = 0; m < HID; m++) s += W2[k * HID + m] * Wl[m * 4 + o];
        g_Wc[idx] = s;
        if (i == NN && t < 4) {
            float v = bl[t];
            #pragma unroll
            for (int m = 0; m < HID; m++) v += b2[m] * Wl[m * 4 + t];
            out[t] = v;
        }
        return;
    }

    cudaGridDependencySynchronize();

    __shared__ float sdv[NN];
    __shared__ float wsum[4 * 5];
    const int wq = t >> 5, lane = t & 31;

    if (t < NN) sdv[t] = g_dv[t];
    __syncthreads();

    float a5[5] = {0.f, 0.f, 0.f, 0.f, 0.f};
    if (t < 115) {
        int k = t + (t >= i);
        int a = min(i, k), b = max(i, k);
        int e = eix(a, b);
        float inv = 1.f / (fmaxf(fmaxf(sdv[i], sdv[k]), 0.f) + 1e-10f);
        #pragma unroll
        for (int c = 0; c < 5; c++) a5[c] = g_gE[e * 5 + c] * inv;
    }
    #pragma unroll
    for (int c = 0; c < 5; c++) {
        #pragma unroll
        for (int off = 16; off; off >>= 1) a5[c] += __shfl_xor_sync(0xffffffffu, a5[c], off);
        if (lane == 0) wsum[wq * 5 + c] = a5[c];
    }
    __syncthreads();
    if (t < 5) g_S[i * 5 + t] = wsum[t] + wsum[5 + t] + wsum[10 + t] + wsum[15 + t];
}

// ============================================================================
// K3 (PDL): D[i]; q[i] = x1[i]@Wc inline; out[o] += D * q[o] / NN.
// Block 0 resets g_done for the next graph replay.
// ============================================================================
__global__ void __launch_bounds__(128, 1) k3(
    const float* __restrict__ be, const float* __restrict__ p2,
    float* __restrict__ out)
{
    cudaGridDependencySynchronize();

    __shared__ float sdv[NN];
    __shared__ float sS[NN * 5];
    __shared__ float sx1r[HID];
    __shared__ float sWc[HID * 4];
    __shared__ float wred[4];
    const int i = blockIdx.x, t = threadIdx.x;
    const int wq = t >> 5, lane = t & 31;

    if (t < NN) sdv[t] = g_dv[t];
    for (int u = t; u < NN * 5; u += 128) sS[u] = g_S[u];
    if (t < HID) sx1r[t] = g_x1[i * HID + t];
    sWc[t] = g_Wc[t];
    sWc[t + 128] = g_Wc[t + 128];
    __syncthreads();

    float dvi = sdv[i];
    float partv = 0.f;
    if (t < 115) {
        int k = t + (t >= i);
        int a = min(i, k), b = max(i, k);
        int e = eix(a, b);
        float dvk = sdv[k];
        float inv = 1.f / (fmaxf(fmaxf(dvi, dvk), 0.f) + 1e-10f);
        #pragma unroll
        for (int c = 0; c < 5; c++) {
            float hh = g_gE[e * 5 + c] * inv;
            float v = dvi * (sS[i * 5 + c] - hh) + dvk * (sS[k * 5 + c] - hh) + __ldg(&be[c]);
            partv += fmaxf(v, 0.f) * __ldg(&p2[c]);
        }
    }
    #pragma unroll
    for (int off = 16; off; off >>= 1) partv += __shfl_xor_sync(0xffffffffu, partv, off);
    if (lane == 0) wred[wq] = partv;
    __syncthreads();

    {
        int o = wq;
        float qv = sx1r[lane] * sWc[lane * 4 + o] + sx1r[lane + 32] * sWc[(lane + 32) * 4 + o];
        #pragma unroll
        for (int off = 16; off; off >>= 1) qv += __shfl_xor_sync(0xffffffffu, qv, off);
        if (lane == 0) {
            float D = wred[0] + wred[1] + wred[2] + wred[3];
            atomicAdd(&out[o], D * qv * (1.0f / (float)NN));
        }
    }

    // reset Wz-producer counter for next replay (strictly after k1 completed)
    if (i == 0 && t == 127) g_done = 0;
}

extern "C" void kernel_launch(void* const* d_in, const int* in_sizes, int n_in,
                              void* d_out, int out_size) {
    const float* enc   = (const float*)d_in[0];
    const float* ea    = (const float*)d_in[1];
    // d_in[2] = edge_index (triu order, closed-form reproduced) — unused
    const float* W_enc = (const float*)d_in[3];
    const float* b_enc = (const float*)d_in[4];
    const float* W1    = (const float*)d_in[5];
    const float* b1    = (const float*)d_in[6];
    const float* p1    = (const float*)d_in[7];
    const float* We    = (const float*)d_in[8];
    const float* be    = (const float*)d_in[9];
    const float* pe    = (const float*)d_in[10];
    const float* W2    = (const float*)d_in[11];
    const float* b2    = (const float*)d_in[12];
    const float* p2    = (const float*)d_in[13];
    const float* Wl    = (const float*)d_in[14];
    const float* bl    = (const float*)d_in[15];
    float* out = (float*)d_out;

    cudaLaunchAttribute attr[1];
    attr[0].id = cudaLaunchAttributeProgrammaticStreamSerialization;
    attr[0].val.programmaticStreamSerializationAllowed = 1;

    k1<<<NN + NWZB, 512>>>(enc, ea, W_enc, b_enc, W1, b1, p1, We, pe);
    {
        cudaLaunchConfig_t cfg = {};
        cfg.gridDim = dim3(NN + 2); cfg.blockDim = dim3(128);
        cfg.attrs = attr; cfg.numAttrs = 1; cfg.stream = 0;
        cudaLaunchKernelEx(&cfg, k2, W2, b2, Wl, bl, out);
    }
    {
        cudaLaunchConfig_t cfg = {};
        cfg.gridDim = dim3(NN); cfg.blockDim = dim3(128);
        cfg.attrs = attr; cfg.numAttrs = 1; cfg.stream = 0;
        cudaLaunchKernelEx(&cfg, k3, be, p2, out);
    }
}

// round 11
// speedup vs baseline: 1.3145x; 1.2973x over previous
#include <cuda_runtime.h>

#define NN   116
#define NE   6670
#define HID  64
#define ENCD 122

// ---- device scratch ----
__device__ float g_gE[NE * 5];
__device__ float g_dv[NN];
__device__ __align__(16) float g_x1[NN * HID];
__device__ __align__(16) float g_Wc[HID * 4];    // W2 @ Wl
__device__ float g_S[NN * 5];

__device__ __forceinline__ int rowoff(int a) { return a * (231 - a) / 2; }
__device__ __forceinline__ int eix(int a, int b) { return rowoff(a) + (b - a - 1); }

// ============================================================================
// K1 (116 x 512): block per node i. ALL global loads batched up front
// (one L2 round trip), then pure smem/FMA stages:
//   d1 -> M = sum_k d1*enc[k,:] -> y = M@[W_enc;b_enc] -> x1 = relu(b1+y... )
// Note: x1 = relu(b1 + (M @ [W_enc;b_enc]) @ W1) done as two smem GEMV stages
// with register-prefetched weights.
// ============================================================================
__global__ void __launch_bounds__(512, 1) k1(
    const float* __restrict__ enc, const float* __restrict__ ea,
    const float* __restrict__ W_enc, const float* __restrict__ b_enc,
    const float* __restrict__ W1, const float* __restrict__ b1,
    const float* __restrict__ p1, const float* __restrict__ We,
    const float* __restrict__ pe)
{
    __shared__ float sd1[116];         // sd1[115] = 0 pad
    __shared__ float sMp[4 * 123];
    __shared__ float sM[128];          // [122]=s_i bias lane, [123..127]=0
    __shared__ float sp[512];
    __shared__ float sy[64];
    __shared__ float sx1[64];

    const int i = blockIdx.x, t = threadIdx.x;
    const int g = t >> 6, m = t & 63;          // y/x1-stage ids
    const int cM = t >> 2, qM = t & 3;         // M-stage ids (t<492)
    const bool m_act = t < 492;

    // ---------- Phase 0: batch-issue ALL global loads ----------
    // edge row
    float a5[5];
    int eg = 0; int ka = 0, kb = 0;
    const bool edge_act = t < 115;
    if (edge_act) {
        int k = t + (t >= i);
        ka = min(i, k); kb = max(i, k);
        eg = eix(ka, kb);
        const float* A = ea + eg * 5;
        #pragma unroll
        for (int c = 0; c < 5; c++) a5[c] = A[c];
    }
    // M-stage enc operands (29 per thread)
    float rE[29];
    #pragma unroll
    for (int j = 0; j < 29; ++j) {
        int u = qM * 29 + j;
        float v = 0.f;
        if (m_act && u < 115) {
            if (cM < 122) {
                int k = u + (u >= i);
                v = enc[k * ENCD + cM];
            } else {
                v = 1.f;                        // bias lane: plain sum of d1
            }
        }
        rE[j] = v;
    }
    // y-stage weights (16 per thread): c = g*16+j, operand [W_enc; b_enc; 0]
    float rWz[16];
    #pragma unroll
    for (int j = 0; j < 16; ++j) {
        int c = g * 16 + j;
        rWz[j] = (c < 122) ? W_enc[c * HID + m] : ((c == 122) ? b_enc[m] : 0.f);
    }
    // x1-stage weights (8 per thread): rows g*8+j of W1
    float rW1[8];
    #pragma unroll
    for (int j = 0; j < 8; ++j) rW1[j] = W1[(g * 8 + j) * HID + m];
    // biases / pe
    float rb1 = (t < 64) ? b1[t] : 0.f;
    float rpe0 = 0.f, rpe1 = 0.f;
    if (t < 32) { rpe0 = pe[t]; rpe1 = pe[t + 32]; }

    // ---------- d1 + gE (consumes a5) ----------
    if (edge_act) {
        float r5[5];
        #pragma unroll
        for (int c = 0; c < 5; c++) r5[c] = fmaxf(a5[c], 0.f);
        sd1[t] = a5[0] * __ldg(&p1[0]) + a5[1] * __ldg(&p1[1]) + a5[2] * __ldg(&p1[2])
               + a5[3] * __ldg(&p1[3]) + a5[4] * __ldg(&p1[4]);
        if (ka == i) {                  // row-owner writes gE once
            #pragma unroll
            for (int c2 = 0; c2 < 5; c2++) {
                float gg = r5[0] * __ldg(&We[c2]) + r5[1] * __ldg(&We[5 + c2])
                         + r5[2] * __ldg(&We[10 + c2]) + r5[3] * __ldg(&We[15 + c2])
                         + r5[4] * __ldg(&We[20 + c2]);
                g_gE[eg * 5 + c2] = gg;
            }
        }
    }
    if (t == 115) sd1[115] = 0.f;
    __syncthreads();

    // ---------- M stage (pure smem/FMA) ----------
    if (m_act) {
        float s = 0.f;
        #pragma unroll
        for (int j = 0; j < 29; ++j) s += rE[j] * sd1[qM * 29 + j];
        sMp[qM * 123 + cM] = s;
    }
    __syncthreads();
    if (t < 123) sM[t] = sMp[t] + sMp[123 + t] + sMp[246 + t] + sMp[369 + t];
    if (t >= 123 && t < 128) sM[t] = 0.f;
    __syncthreads();

    // ---------- y = M @ [W_enc; b_enc; 0] ----------
    {
        float s = 0.f;
        #pragma unroll
        for (int j = 0; j < 16; ++j) s += sM[g * 16 + j] * rWz[j];
        sp[g * 64 + m] = s;
    }
    __syncthreads();
    if (t < HID) {
        float s = sp[t];
        #pragma unroll
        for (int gg = 1; gg < 8; ++gg) s += sp[gg * 64 + t];
        sy[t] = s;
    }
    __syncthreads();

    // ---------- x1 = relu(b1 + y @ W1) ----------
    {
        float s = 0.f;
        #pragma unroll
        for (int j = 0; j < 8; ++j) s += sy[g * 8 + j] * rW1[j];
        sp[g * 64 + m] = s;
    }
    __syncthreads();
    if (t < HID) {
        float s = sp[t];
        #pragma unroll
        for (int gg = 1; gg < 8; ++gg) s += sp[gg * 64 + t];
        float x = fmaxf(rb1 + s, 0.f);
        sx1[t] = x;
        g_x1[i * HID + t] = x;
    }
    __syncthreads();

    // ---------- dv = x1 . pe ----------
    if (t < 32) {
        float s = sx1[t] * rpe0 + sx1[t + 32] * rpe1;
        #pragma unroll
        for (int off = 16; off; off >>= 1) s += __shfl_xor_sync(0xffffffffu, s, off);
        if (t == 0) g_dv[i] = s;
    }
}

// ============================================================================
// K2 (PDL): blocks 0..115: S[i,c] (gE and dv loads batched after sync);
// blocks 116,117: Wc = W2@Wl + bias seed (independent, no sync).
// ============================================================================
__global__ void __launch_bounds__(128, 1) k2(
    const float* __restrict__ W2, const float* __restrict__ b2,
    const float* __restrict__ Wl, const float* __restrict__ bl,
    float* __restrict__ out)
{
    const int i = blockIdx.x, t = threadIdx.x;

    if (i >= NN) {
        int idx = (i - NN) * 128 + t;    // 0..255
        int k = idx >> 2, o = idx & 3;
        float s = 0.f;
        #pragma unroll
        for (int mm = 0; mm < HID; mm++) s += W2[k * HID + mm] * Wl[mm * 4 + o];
        g_Wc[idx] = s;
        if (i == NN && t < 4) {
            float v = bl[t];
            #pragma unroll
            for (int mm = 0; mm < HID; mm++) v += b2[mm] * Wl[mm * 4 + t];
            out[t] = v;
        }
        return;
    }

    cudaGridDependencySynchronize();

    __shared__ float sdv[NN];
    __shared__ float wsum[4 * 5];
    const int wq = t >> 5, lane = t & 31;

    // batch loads: gE row (5) and dv — independent, one round trip
    float a5[5] = {0.f, 0.f, 0.f, 0.f, 0.f};
    int kn = 0;
    if (t < 115) {
        kn = t + (t >= i);
        int a = min(i, kn), b = max(i, kn);
        int e = eix(a, b);
        #pragma unroll
        for (int c = 0; c < 5; c++) a5[c] = g_gE[e * 5 + c];
    }
    if (t < NN) sdv[t] = g_dv[t];
    __syncthreads();

    float s5[5] = {0.f, 0.f, 0.f, 0.f, 0.f};
    if (t < 115) {
        float inv = 1.f / (fmaxf(fmaxf(sdv[i], sdv[kn]), 0.f) + 1e-10f);
        #pragma unroll
        for (int c = 0; c < 5; c++) s5[c] = a5[c] * inv;
    }
    #pragma unroll
    for (int c = 0; c < 5; c++) {
        #pragma unroll
        for (int off = 16; off; off >>= 1) s5[c] += __shfl_xor_sync(0xffffffffu, s5[c], off);
        if (lane == 0) wsum[wq * 5 + c] = s5[c];
    }
    __syncthreads();
    if (t < 5) g_S[i * 5 + t] = wsum[t] + wsum[5 + t] + wsum[10 + t] + wsum[15 + t];
}

// ============================================================================
// K3 (PDL): D[i]; q[i] = x1[i]@Wc inline; out[o] += D * q[o] / NN.
// All global loads batched right after the dependency sync.
// ============================================================================
__global__ void __launch_bounds__(128, 1) k3(
    const float* __restrict__ be, const float* __restrict__ p2,
    float* __restrict__ out)
{
    cudaGridDependencySynchronize();

    __shared__ float sdv[NN];
    __shared__ float sS[NN * 5];
    __shared__ float sx1r[HID];
    __shared__ float sWc[HID * 4];
    __shared__ float wred[4];
    const int i = blockIdx.x, t = threadIdx.x;
    const int wq = t >> 5, lane = t & 31;

    // batch-issue everything: gE row, dv, S, x1, Wc, be, p2
    float a5[5] = {0.f, 0.f, 0.f, 0.f, 0.f};
    int kn = 0;
    if (t < 115) {
        kn = t + (t >= i);
        int a = min(i, kn), b = max(i, kn);
        int e = eix(a, b);
        #pragma unroll
        for (int c = 0; c < 5; c++) a5[c] = g_gE[e * 5 + c];
    }
    if (t < NN) sdv[t] = g_dv[t];
    #pragma unroll
    for (int r = 0; r < 5; ++r) {
        int u = t + r * 128;
        if (u < NN * 5) sS[u] = g_S[u];
    }
    if (t < HID) sx1r[t] = g_x1[i * HID + t];
    sWc[t] = g_Wc[t];
    sWc[t + 128] = g_Wc[t + 128];
    float rbe[5], rp2[5];
    #pragma unroll
    for (int c = 0; c < 5; c++) { rbe[c] = __ldg(&be[c]); rp2[c] = __ldg(&p2[c]); }
    __syncthreads();

    float dvi = sdv[i];
    float partv = 0.f;
    if (t < 115) {
        float dvk = sdv[kn];
        float inv = 1.f / (fmaxf(fmaxf(dvi, dvk), 0.f) + 1e-10f);
        #pragma unroll
        for (int c = 0; c < 5; c++) {
            float hh = a5[c] * inv;
            float v = dvi * (sS[i * 5 + c] - hh) + dvk * (sS[kn * 5 + c] - hh) + rbe[c];
            partv += fmaxf(v, 0.f) * rp2[c];
        }
    }
    #pragma unroll
    for (int off = 16; off; off >>= 1) partv += __shfl_xor_sync(0xffffffffu, partv, off);
    if (lane == 0) wred[wq] = partv;
    __syncthreads();

    {
        int o = wq;
        float qv = sx1r[lane] * sWc[lane * 4 + o] + sx1r[lane + 32] * sWc[(lane + 32) * 4 + o];
        #pragma unroll
        for (int off = 16; off; off >>= 1) qv += __shfl_xor_sync(0xffffffffu, qv, off);
        if (lane == 0) {
            float D = wred[0] + wred[1] + wred[2] + wred[3];
            atomicAdd(&out[o], D * qv * (1.0f / (float)NN));
        }
    }
}

extern "C" void kernel_launch(void* const* d_in, const int* in_sizes, int n_in,
                              void* d_out, int out_size) {
    const float* enc   = (const float*)d_in[0];
    const float* ea    = (const float*)d_in[1];
    // d_in[2] = edge_index (triu order, closed-form reproduced) — unused
    const float* W_enc = (const float*)d_in[3];
    const float* b_enc = (const float*)d_in[4];
    const float* W1    = (const float*)d_in[5];
    const float* b1    = (const float*)d_in[6];
    const float* p1    = (const float*)d_in[7];
    const float* We    = (const float*)d_in[8];
    const float* be    = (const float*)d_in[9];
    const float* pe    = (const float*)d_in[10];
    const float* W2    = (const float*)d_in[11];
    const float* b2    = (const float*)d_in[12];
    const float* p2    = (const float*)d_in[13];
    const float* Wl    = (const float*)d_in[14];
    const float* bl    = (const float*)d_in[15];
    float* out = (float*)d_out;

    cudaLaunchAttribute attr[1];
    attr[0].id = cudaLaunchAttributeProgrammaticStreamSerialization;
    attr[0].val.programmaticStreamSerializationAllowed = 1;

    k1<<<NN, 512>>>(enc, ea, W_enc, b_enc, W1, b1, p1, We, pe);
    {
        cudaLaunchConfig_t cfg = {};
        cfg.gridDim = dim3(NN + 2); cfg.blockDim = dim3(128);
        cfg.attrs = attr; cfg.numAttrs = 1; cfg.stream = 0;
        cudaLaunchKernelEx(&cfg, k2, W2, b2, Wl, bl, out);
    }
    {
        cudaLaunchConfig_t cfg = {};
        cfg.gridDim = dim3(NN); cfg.blockDim = dim3(128);
        cfg.attrs = attr; cfg.numAttrs = 1; cfg.stream = 0;
        cudaLaunchKernelEx(&cfg, k3, be, p2, out);
    }
}